// round 5
// baseline (speedup 1.0000x reference)
#include <cuda_runtime.h>
#include <math.h>

#define GX 256
#define GY 256
#define NBATCH 4
#define SENTKEY (NBATCH*GX*GY)        /* 262144 */
#define NKEY (SENTKEY+1)              /* 262145 */
#define NSEG (SENTKEY+2)              /* 262146 */
#define MAXN 1000000
#define NBLK ((NKEY+1023)/1024)       /* 257 */
#define BN_EPS 1e-3f
#define FULLMASK 0xffffffffu
#define ENC_NEG_INF 0x007FFFFFu

// ---------------- static scratch ----------------
static __device__ int   g_keys[MAXN];
static __device__ int   g_order[MAXN];
static __device__ int   g_segof[MAXN];
static __device__ int   g_cnt[NKEY];
static __device__ int   g_cursor[NKEY];
static __device__ int   g_rank[NKEY];
static __device__ int   g_off[NKEY];
static __device__ float g_sumxyz[NKEY*3];
static __device__ int   g_blkP[NBLK], g_blkC[NBLK], g_offP[NBLK], g_offC[NBLK];
static __device__ int   g_U, g_sentseg, g_nsent;
static __device__ int   g_segstart[NSEG], g_segcnt[NSEG], g_keyofrank[NSEG];
static __device__ float g_mean[NSEG*3];
static __device__ double g_sum0d[32], g_sumsq0d[32];
static __device__ float g_a0[32], g_b0v[32];
static __device__ double g_sumzd[128], g_sumz2d[128];
static __device__ float g_a1[128], g_b1v[128];
static __device__ float    g_x0all[(size_t)MAXN*32];      // 128 MB
static __device__ float    g_xm0[(size_t)NSEG*32];        // 34 MB
static __device__ float    g_zb[(size_t)NSEG*128];        // 134 MB
static __device__ unsigned g_pre_u[(size_t)NSEG*128];     // 134 MB

static __device__ __forceinline__ unsigned encf(float f){
    unsigned b = __float_as_uint(f);
    return (b & 0x80000000u) ? ~b : (b | 0x80000000u);
}
static __device__ __forceinline__ float decf(unsigned e){
    unsigned b = (e & 0x80000000u) ? (e & 0x7FFFFFFFu) : ~e;
    return __uint_as_float(b);
}

// ---------------- init ----------------
__global__ void kInit(){
    int i = blockIdx.x*blockDim.x + threadIdx.x;
    int stride = gridDim.x*blockDim.x;
    for (int idx=i; idx<NKEY*3; idx+=stride) g_sumxyz[idx]=0.f;
    for (int idx=i; idx<NKEY; idx+=stride){ g_cnt[idx]=0; g_cursor[idx]=0; }
    for (size_t idx=i; idx<(size_t)NSEG*128; idx+=stride) g_pre_u[idx]=ENC_NEG_INF;
    if (i < 128){ g_sumzd[i]=0.0; g_sumz2d[i]=0.0; }
    if (i < 32){ g_sum0d[i]=0.0; g_sumsq0d[i]=0.0; }
    if (i == 0){ g_sentseg=-1; g_nsent=0; }
}

__global__ void kFill(float* __restrict__ out){
    int i = blockIdx.x*blockDim.x + threadIdx.x;
    int stride = gridDim.x*blockDim.x;
    float* oc = out + (size_t)NSEG*128;
    for (int r=i; r<NSEG; r+=stride){
        oc[(size_t)r*3+0]=4.0f; oc[(size_t)r*3+1]=0.0f; oc[(size_t)r*3+2]=0.0f;
    }
    if (i==0){
        out[(size_t)NSEG*128 + (size_t)NSEG*3 + 0] = 256.0f;
        out[(size_t)NSEG*128 + (size_t)NSEG*3 + 1] = 256.0f;
    }
}

// ---------------- A: keys + histogram + xyz sums ----------------
__global__ void kA(const float* __restrict__ pts, int n){
    int i = blockIdx.x*blockDim.x + threadIdx.x;
    int stride = gridDim.x*blockDim.x;
    for (int p=i; p<n; p+=stride){
        const float* q = pts + (size_t)p*6;
        float b=q[0], x=q[1], y=q[2], z=q[3];
        float fx = __fdiv_rn(x - (-51.2f), 0.4f);
        float fy = __fdiv_rn(y - (-51.2f), 0.4f);
        bool m = (fx >= 0.f) && (fx < 256.f) && (fy >= 0.f) && (fy < 256.f);
        int cix=(int)fx, ciy=(int)fy;
        int bi=(int)b;
        int key = m ? ((bi*GX + cix)*GY + ciy) : SENTKEY;
        g_keys[p]=key;
        atomicAdd(&g_cnt[key],1);
        atomicAdd(&g_sumxyz[key*3+0],x);
        atomicAdd(&g_sumxyz[key*3+1],y);
        atomicAdd(&g_sumxyz[key*3+2],z);
    }
}

// ---------------- B: two-level scan over keys ----------------
__global__ void kB1(){
    int tid = threadIdx.x;
    int idx = blockIdx.x*1024 + tid;
    int c = (idx<NKEY)? g_cnt[idx] : 0;
    int p = (c>0)? 1:0;
    #pragma unroll
    for (int o=16;o;o>>=1){ p+=__shfl_down_sync(FULLMASK,p,o); c+=__shfl_down_sync(FULLMASK,c,o); }
    __shared__ int sp[32], sc[32];
    if ((tid&31)==0){ sp[tid>>5]=p; sc[tid>>5]=c; }
    __syncthreads();
    if (tid<32){
        p=sp[tid]; c=sc[tid];
        #pragma unroll
        for (int o=16;o;o>>=1){ p+=__shfl_down_sync(FULLMASK,p,o); c+=__shfl_down_sync(FULLMASK,c,o); }
        if (tid==0){ g_blkP[blockIdx.x]=p; g_blkC[blockIdx.x]=c; }
    }
}

__global__ void kB2(){
    __shared__ int sp[512], sc[512];
    int t = threadIdx.x;
    int p = (t<NBLK)? g_blkP[t]:0;
    int c = (t<NBLK)? g_blkC[t]:0;
    sp[t]=p; sc[t]=c; __syncthreads();
    for (int o=1;o<512;o<<=1){
        int vp=(t>=o)?sp[t-o]:0, vc=(t>=o)?sc[t-o]:0;
        __syncthreads();
        sp[t]+=vp; sc[t]+=vc;
        __syncthreads();
    }
    if (t<NBLK){ g_offP[t]=sp[t]-p; g_offC[t]=sc[t]-c; }
    if (t==NBLK-1) g_U = sp[t];
}

__global__ void kB3(float* __restrict__ out){
    __shared__ int sp[1024], sc[1024];
    int tid = threadIdx.x;
    int idx = blockIdx.x*1024 + tid;
    int c = (idx<NKEY)? g_cnt[idx]:0;
    int pr = (c>0)? 1:0;
    sp[tid]=pr; sc[tid]=c; __syncthreads();
    for (int o=1;o<1024;o<<=1){
        int vp=(tid>=o)?sp[tid-o]:0, vc=(tid>=o)?sc[tid-o]:0;
        __syncthreads();
        sp[tid]+=vp; sc[tid]+=vc;
        __syncthreads();
    }
    if (idx<NKEY){
        int r  = sp[tid]-pr + g_offP[blockIdx.x];
        int of = sc[tid]-c  + g_offC[blockIdx.x];
        g_rank[idx]=r; g_off[idx]=of;
        if (pr){
            g_keyofrank[r]=idx; g_segstart[r]=of; g_segcnt[r]=c;
            float fc = (float)c;
            g_mean[r*3+0]=__fdiv_rn(g_sumxyz[idx*3+0],fc);
            g_mean[r*3+1]=__fdiv_rn(g_sumxyz[idx*3+1],fc);
            g_mean[r*3+2]=__fdiv_rn(g_sumxyz[idx*3+2],fc);
            int b=idx>>16, cx=(idx>>8)&255, cy=idx&255;
            float* oc = out + (size_t)NSEG*128 + (size_t)r*3;
            oc[0]=(float)b; oc[1]=(float)cy; oc[2]=(float)cx;
            if (idx==SENTKEY){ g_sentseg=r; g_nsent=c; }
        }
    }
}

__global__ void kZeroSent(){
    int ss = g_sentseg;
    if (ss >= 0) g_xm0[(size_t)ss*32 + threadIdx.x] = 0.f;
}

// ---------------- C: counting-sort scatter + segof ----------------
__global__ void kC(int n){
    int i = blockIdx.x*blockDim.x + threadIdx.x;
    int stride = gridDim.x*blockDim.x;
    for (int p=i; p<n; p+=stride){
        int key = g_keys[p];
        int pos = g_off[key] + atomicAdd(&g_cursor[key],1);
        g_order[pos] = p;
        g_segof[pos] = g_rank[key];
    }
}

// pre-affine x0 for a point
static __device__ __forceinline__ float compX0(const float* __restrict__ pts, int p,
    float mx, float my, float mzv, float ccx, float ccy, const float* __restrict__ w0c)
{
    const float2* q = reinterpret_cast<const float2*>(pts + (size_t)p*6);
    float2 q0=__ldg(q), q1=__ldg(q+1), q2=__ldg(q+2);
    float x=q0.y, y=q1.x, z=q1.y;
    float s =  x*w0c[0] + y*w0c[1] + z*w0c[2] + q2.x*w0c[3] + q2.y*w0c[4]
            + (x-mx)*w0c[5] + (y-my)*w0c[6] + (z-mzv)*w0c[7]
            + (x-ccx)*w0c[8] + (y-ccy)*w0c[9];
    return s;
}

// ---------------- BN0 stats over valid points (double accumulation) ----------------
__global__ void __launch_bounds__(256) kBN0(const float* __restrict__ pts,
                                            const float* __restrict__ w0, int n){
    int gtid = blockIdx.x*blockDim.x + threadIdx.x;
    int w = gtid>>5, lane = gtid&31;
    int nwarps = (gridDim.x*blockDim.x)>>5;
    float w0c[10];
    #pragma unroll
    for (int j=0;j<10;j++) w0c[j]=w0[j*32+lane];
    double s=0.0, s2=0.0;
    for (int p=w; p<n; p+=nwarps){
        int key = g_keys[p];
        if (key == SENTKEY) continue;
        int r = g_rank[key];
        float mx=g_mean[r*3+0], my=g_mean[r*3+1], mzv=g_mean[r*3+2];
        float ccx=(float)((key>>8)&255)*0.4f + 0.2f + (-51.2f);
        float ccy=(float)(key&255)*0.4f + 0.2f + (-51.2f);
        float x0 = compX0(pts,p,mx,my,mzv,ccx,ccy,w0c);
        s += (double)x0; s2 += (double)x0*(double)x0;
    }
    atomicAdd(&g_sum0d[lane], s);
    atomicAdd(&g_sumsq0d[lane], s2);
}

// ---------------- BN0 params ----------------
__global__ void kD1(const float* __restrict__ g0, const float* __restrict__ b0, int n){
    int c = threadIdx.x; // 32
    double cnt = (double)(n - g_cnt[SENTKEY]);
    double mu = g_sum0d[c]/cnt;
    double var = g_sumsq0d[c]/cnt - mu*mu;
    if (var < 0.0) var = 0.0;
    float a = g0[c] / sqrtf((float)var + BN_EPS);
    g_a0[c]=a; g_b0v[c]=b0[c]-(float)mu*a;
}

// ---------------- M1: warp per valid segment -> x0all + xm0 ----------------
__global__ void __launch_bounds__(256) kM1(const float* __restrict__ pts,
                                           const float* __restrict__ w0){
    int gtid = blockIdx.x*blockDim.x + threadIdx.x;
    int w = gtid>>5, lane = gtid&31;
    int nwarps = (gridDim.x*blockDim.x)>>5;
    int U = g_U, sentseg = g_sentseg;
    float w0c[10];
    #pragma unroll
    for (int j=0;j<10;j++) w0c[j]=w0[j*32+lane];
    float a0=g_a0[lane], b0v=g_b0v[lane];
    for (int r=w; r<U; r+=nwarps){
        if (r==sentseg) continue;
        int st=g_segstart[r], cn=g_segcnt[r], key=g_keyofrank[r];
        float mx=g_mean[r*3+0], my=g_mean[r*3+1], mzv=g_mean[r*3+2];
        float ccx=(float)((key>>8)&255)*0.4f + 0.2f + (-51.2f);
        float ccy=(float)(key&255)*0.4f + 0.2f + (-51.2f);
        float run0 = 0.f;
        for (int i=0;i<cn;i++){
            int pos = st+i;
            int p = g_order[pos];
            float x0r = fmaxf(a0*compX0(pts,p,mx,my,mzv,ccx,ccy,w0c) + b0v, 0.f);
            g_x0all[(size_t)pos*32 + lane] = x0r;
            run0 = fmaxf(run0, x0r);
        }
        g_xm0[(size_t)r*32 + lane] = run0;
    }
}

// ---------------- M1s: sentinel points -> x0all + xm0[sentseg] ----------------
__global__ void __launch_bounds__(256) kM1s(const float* __restrict__ pts,
                                            const float* __restrict__ w0){
    int nsent = g_nsent;
    if (nsent == 0) return;
    int ss = g_sentseg;
    int st = g_segstart[ss];
    int gtid = blockIdx.x*blockDim.x + threadIdx.x;
    int w = gtid>>5, lane = gtid&31;
    int nwarps = (gridDim.x*blockDim.x)>>5;
    float mx=g_mean[ss*3+0], my=g_mean[ss*3+1], mzv=g_mean[ss*3+2];
    float w0c[10];
    #pragma unroll
    for (int j=0;j<10;j++) w0c[j]=w0[j*32+lane];
    float a0=g_a0[lane], b0v=g_b0v[lane];
    float runmax = 0.f;
    for (int i=w; i<nsent; i+=nwarps){
        int pos = st+i;
        int p = g_order[pos];
        const float2* q = reinterpret_cast<const float2*>(pts + (size_t)p*6);
        float2 q0=__ldg(q), q1=__ldg(q+1);
        float x=q0.y, y=q1.x;
        float fx=__fdiv_rn(x - (-51.2f), 0.4f);
        float fy=__fdiv_rn(y - (-51.2f), 0.4f);
        int cix=(int)fx, ciy=(int)fy;
        float ccx=(float)cix*0.4f + 0.2f + (-51.2f);
        float ccy=(float)ciy*0.4f + 0.2f + (-51.2f);
        float x0r = fmaxf(a0*compX0(pts,p,mx,my,mzv,ccx,ccy,w0c) + b0v, 0.f);
        g_x0all[(size_t)pos*32 + lane] = x0r;
        runmax = fmaxf(runmax, x0r);
    }
    atomicMax((int*)&g_xm0[(size_t)ss*32 + lane], __float_as_int(runmax));
}

// ---------------- ZB: per-segment zb = xm0 @ w1b (tiled GEMM) ----------------
__global__ void __launch_bounds__(256) kZB(const float* __restrict__ w1){
    __shared__ float xs[32*136];
    __shared__ float ws[32*128];
    int U = g_U;
    int base = blockIdx.x*128;
    if (base >= U) return;
    int ns = min(128, U - base);
    int tid = threadIdx.x;
    for (int i=tid; i<1024; i+=256)
        reinterpret_cast<float4*>(ws)[i] = reinterpret_cast<const float4*>(w1)[1024+i]; // w1 rows 32..63
    for (int i=tid; i<1024; i+=256){
        int s = i>>3, q = i&7;
        float4 v = (s<ns) ? reinterpret_cast<const float4*>(g_xm0 + (size_t)(base+s)*32)[q]
                          : make_float4(0.f,0.f,0.f,0.f);
        xs[(q*4+0)*136+s]=v.x; xs[(q*4+1)*136+s]=v.y; xs[(q*4+2)*136+s]=v.z; xs[(q*4+3)*136+s]=v.w;
    }
    __syncthreads();
    int tc = tid & 15, tp = tid >> 4;
    float acc[8][8];
    #pragma unroll
    for (int i=0;i<8;i++)
        #pragma unroll
        for (int j=0;j<8;j++) acc[i][j]=0.f;
    #pragma unroll 8
    for (int k=0;k<32;k++){
        float4 a0 = *reinterpret_cast<float4*>(&xs[k*136 + tp*8]);
        float4 a1 = *reinterpret_cast<float4*>(&xs[k*136 + tp*8 + 4]);
        float4 b0 = *reinterpret_cast<float4*>(&ws[k*128 + tc*8]);
        float4 b1 = *reinterpret_cast<float4*>(&ws[k*128 + tc*8 + 4]);
        float a[8]={a0.x,a0.y,a0.z,a0.w,a1.x,a1.y,a1.z,a1.w};
        float b[8]={b0.x,b0.y,b0.z,b0.w,b1.x,b1.y,b1.z,b1.w};
        #pragma unroll
        for (int i=0;i<8;i++)
            #pragma unroll
            for (int j=0;j<8;j++) acc[i][j] = fmaf(a[i], b[j], acc[i][j]);
    }
    #pragma unroll
    for (int i=0;i<8;i++){
        int s = tp*8 + i;
        if (s < ns){
            float* dst = g_zb + (size_t)(base+s)*128 + tc*8;
            *reinterpret_cast<float4*>(dst)   = make_float4(acc[i][0],acc[i][1],acc[i][2],acc[i][3]);
            *reinterpret_cast<float4*>(dst+4) = make_float4(acc[i][4],acc[i][5],acc[i][6],acc[i][7]);
        }
    }
}

// ---------------- M2: za GEMM + fused segmented max + BN1 stats ----------------
#define M2_SMEM_BYTES 88592
__global__ void __launch_bounds__(256) kM2(const float* __restrict__ w1, int n){
    extern __shared__ float dsm[];
    float* zs  = dsm;                  // 128*132 floats
    float* x0s = dsm;                  // alias of zs; fully consumed before zs is written
    float* w1s = zs + 128*132;         // 4096 floats (w1a = rows 0..31)
    int*   segs = (int*)(w1s + 4096);  // 132 ints
    double* sredA = (double*)(segs + 132); // 256 doubles
    double* sredB = sredA + 256;           // 256 doubles

    int tid = threadIdx.x;
    int base = blockIdx.x * 128;
    if (base >= n) return;
    int npts = min(128, n - base);

    for (int i=tid; i<1024; i+=256)
        reinterpret_cast<float4*>(w1s)[i] = reinterpret_cast<const float4*>(w1)[i];
    for (int i=tid; i<1024; i+=256){
        int pt = i>>3, q = i&7;
        float4 v = (pt<npts) ? reinterpret_cast<const float4*>(g_x0all + (size_t)(base+pt)*32)[q]
                             : make_float4(0.f,0.f,0.f,0.f);
        x0s[(q*4+0)*136+pt]=v.x; x0s[(q*4+1)*136+pt]=v.y; x0s[(q*4+2)*136+pt]=v.z; x0s[(q*4+3)*136+pt]=v.w;
    }
    for (int i=tid; i<130; i+=256){
        int g = base + i - 1;
        segs[i] = (g >= 0 && g < n) ? g_segof[g] : -1;
    }
    __syncthreads();

    int tc = tid & 15, tp = tid >> 4;
    float acc[8][8];
    #pragma unroll
    for (int i=0;i<8;i++)
        #pragma unroll
        for (int j=0;j<8;j++) acc[i][j]=0.f;
    #pragma unroll 8
    for (int k=0;k<32;k++){
        float4 a0 = *reinterpret_cast<float4*>(&x0s[k*136 + tp*8]);
        float4 a1 = *reinterpret_cast<float4*>(&x0s[k*136 + tp*8 + 4]);
        float4 b0 = *reinterpret_cast<float4*>(&w1s[k*128 + tc*8]);
        float4 b1 = *reinterpret_cast<float4*>(&w1s[k*128 + tc*8 + 4]);
        float a[8]={a0.x,a0.y,a0.z,a0.w,a1.x,a1.y,a1.z,a1.w};
        float b[8]={b0.x,b0.y,b0.z,b0.w,b1.x,b1.y,b1.z,b1.w};
        #pragma unroll
        for (int i=0;i<8;i++)
            #pragma unroll
            for (int j=0;j<8;j++) acc[i][j] = fmaf(a[i], b[j], acc[i][j]);
    }
    __syncthreads();   // all x0s reads done before aliased zs writes
    #pragma unroll
    for (int i=0;i<8;i++){
        float* dst = &zs[(tp*8+i)*132 + tc*8];
        *reinterpret_cast<float4*>(dst)   = make_float4(acc[i][0],acc[i][1],acc[i][2],acc[i][3]);
        *reinterpret_cast<float4*>(dst+4) = make_float4(acc[i][4],acc[i][5],acc[i][6],acc[i][7]);
    }
    __syncthreads();

    // segmented scan: thread = (channel c, half h), up to 64 points serial
    int c = tid & 127, h = tid >> 7;
    int l0 = h*64, l1 = min(l0+64, npts);
    double sz = 0.0, sz2 = 0.0;
    if (l0 < l1){
        int nvalid = n - g_nsent;
        int rcur = segs[l0+1];
        bool openL = (segs[l0] == rcur);
        float zb = g_zb[(size_t)rcur*128 + c];
        float mza = -INFINITY;
        for (int i=l0; i<l1; i++){
            float za = zs[i*132 + c];
            float z = za + zb;
            if (base + i < nvalid){ sz += (double)z; sz2 += (double)z*(double)z; }
            mza = fmaxf(mza, za);
            int rn = segs[i+2];
            bool last = (i == l1-1);
            if (rn != rcur || last){
                bool openR = last && (rn == rcur);
                unsigned e = encf(mza + zb);
                unsigned* dst = &g_pre_u[(size_t)rcur*128 + c];
                if (openL | openR) atomicMax(dst, e);
                else *dst = e;
                if (!last && rn != rcur){
                    rcur = rn;
                    zb = g_zb[(size_t)rcur*128 + c];
                    mza = -INFINITY;
                    openL = false;
                }
            }
        }
    }
    sredA[tid] = sz; sredB[tid] = sz2;
    __syncthreads();
    if (tid < 128){
        double a = sredA[tid] + sredA[tid+128];
        double b = sredB[tid] + sredB[tid+128];
        atomicAdd(&g_sumzd[tid], a);
        atomicAdd(&g_sumz2d[tid], b);
    }
}

// ---------------- BN1 params ----------------
__global__ void kE1(const float* __restrict__ g1, const float* __restrict__ b1, int n){
    int c = threadIdx.x; // 128
    double cnt = (double)(n - g_cnt[SENTKEY]);
    double mu = g_sumzd[c]/cnt;
    double var = g_sumz2d[c]/cnt - mu*mu;
    if (var < 0.0) var = 0.0;
    float a = g1[c] / sqrtf((float)var + BN_EPS);
    g_a1[c]=a; g_b1v[c]=b1[c]-(float)mu*a;
}

// ---------------- final output ----------------
__global__ void kFinal(float* __restrict__ out){
    int i = blockIdx.x*blockDim.x + threadIdx.x;
    int stride = gridDim.x*blockDim.x;
    int U = g_U;
    const size_t total = (size_t)NSEG*128;
    for (size_t idx=i; idx<total; idx+=stride){
        int r = (int)(idx>>7), c = (int)(idx&127);
        float v = 0.f;
        if (r < U){
            float z = decf(g_pre_u[idx]);
            v = fmaxf(g_a1[c]*z + g_b1v[c], 0.f);
        }
        out[idx] = v;
    }
}

extern "C" void kernel_launch(void* const* d_in, const int* in_sizes, int n_in,
                              void* d_out, int out_size) {
    const float* pts = (const float*)d_in[0];
    const float* w0  = (const float*)d_in[1];
    const float* g0  = (const float*)d_in[2];
    const float* b0  = (const float*)d_in[3];
    const float* w1  = (const float*)d_in[4];
    const float* g1  = (const float*)d_in[5];
    const float* b1  = (const float*)d_in[6];
    float* out = (float*)d_out;
    int n = in_sizes[0] / 6;
    if (n > MAXN) n = MAXN;
    if (n <= 0) return;

    (void)cudaFuncSetAttribute(kM2, cudaFuncAttributeMaxDynamicSharedMemorySize, M2_SMEM_BYTES);
    (void)cudaGetLastError();   // clear any benign error before capture-sensitive launches

    kInit<<<4096, 256>>>();
    kFill<<<1024, 256>>>(out);
    kA<<<2048, 256>>>(pts, n);
    kB1<<<NBLK, 1024>>>();
    kB2<<<1, 512>>>();
    kB3<<<NBLK, 1024>>>(out);
    kZeroSent<<<1, 32>>>();
    kC<<<2048, 256>>>(n);
    kBN0<<<1024, 256>>>(pts, w0, n);
    kD1<<<1, 32>>>(g0, b0, n);
    kM1<<<1024, 256>>>(pts, w0);
    kM1s<<<512, 256>>>(pts, w0);
    kZB<<<(NSEG+127)/128, 256>>>(w1);
    kM2<<<(n+127)/128, 256, M2_SMEM_BYTES>>>(w1, n);
    kE1<<<1, 128>>>(g1, b1, n);
    kFinal<<<8192, 256>>>(out);
}

// round 6
// speedup vs baseline: 1.0411x; 1.0411x over previous
#include <cuda_runtime.h>
#include <math.h>

#define GX 256
#define GY 256
#define NBATCH 4
#define SENTKEY (NBATCH*GX*GY)        /* 262144 */
#define NKEY (SENTKEY+1)              /* 262145 */
#define NSEG (SENTKEY+2)              /* 262146 */
#define MAXN 1000000
#define NBLK ((NKEY+1023)/1024)       /* 257 */
#define NB_CX 1184
#define NB_M2 ((MAXN+127)/128)        /* 7813 */
#define BN_EPS 1e-3f
#define FULLMASK 0xffffffffu
#define ENC_NEG_INF 0x007FFFFFu

// ---------------- static scratch ----------------
static __device__ int   g_keys[MAXN];
static __device__ int   g_segof[MAXN];
static __device__ int   g_cnt[NKEY];
static __device__ int   g_cursor[NKEY];
static __device__ int   g_rank[NKEY];
static __device__ int   g_off[NKEY];
static __device__ float g_sumxyz[NKEY*3];
static __device__ int   g_blkP[NBLK], g_blkC[NBLK], g_offP[NBLK], g_offC[NBLK];
static __device__ int   g_U, g_sentseg, g_nsent;
static __device__ int   g_segstart[NSEG], g_segcnt[NSEG], g_keyofrank[NSEG];
static __device__ float g_mean[NSEG*3];
static __device__ float g_a0[32], g_b0v[32];
static __device__ float g_a1[128], g_b1v[128];
static __device__ float g_bn0part[NB_CX*64];
static __device__ float g_bn1part[(size_t)NB_M2*256];
static __device__ float    g_x0all[(size_t)MAXN*32];      // 128 MB (pre-affine x0, sorted order)
static __device__ unsigned g_xm0u[(size_t)NSEG*32];       // 34 MB (encoded per-seg max of pre-affine x0)
static __device__ float    g_zb[(size_t)NSEG*128];        // 134 MB
static __device__ unsigned g_pre_u[(size_t)NSEG*128];     // 134 MB

static __device__ __forceinline__ unsigned encf(float f){
    unsigned b = __float_as_uint(f);
    return (b & 0x80000000u) ? ~b : (b | 0x80000000u);
}
static __device__ __forceinline__ float decf(unsigned e){
    unsigned b = (e & 0x80000000u) ? (e & 0x7FFFFFFFu) : ~e;
    return __uint_as_float(b);
}

// ---------------- init ----------------
__global__ void kInit(){
    int i = blockIdx.x*blockDim.x + threadIdx.x;
    int stride = gridDim.x*blockDim.x;
    for (int idx=i; idx<NKEY*3; idx+=stride) g_sumxyz[idx]=0.f;
    for (int idx=i; idx<NKEY; idx+=stride){ g_cnt[idx]=0; g_cursor[idx]=0; }
    for (size_t idx=i; idx<(size_t)NSEG*128; idx+=stride) g_pre_u[idx]=ENC_NEG_INF;
    if (i == 0){ g_sentseg=-1; g_nsent=0; }
}

__global__ void kFill(float* __restrict__ out){
    int i = blockIdx.x*blockDim.x + threadIdx.x;
    int stride = gridDim.x*blockDim.x;
    float* oc = out + (size_t)NSEG*128;
    for (int r=i; r<NSEG; r+=stride){
        oc[(size_t)r*3+0]=4.0f; oc[(size_t)r*3+1]=0.0f; oc[(size_t)r*3+2]=0.0f;
    }
    if (i==0){
        out[(size_t)NSEG*128 + (size_t)NSEG*3 + 0] = 256.0f;
        out[(size_t)NSEG*128 + (size_t)NSEG*3 + 1] = 256.0f;
    }
}

// ---------------- A: keys + histogram + xyz sums ----------------
__global__ void kA(const float* __restrict__ pts, int n){
    int i = blockIdx.x*blockDim.x + threadIdx.x;
    int stride = gridDim.x*blockDim.x;
    for (int p=i; p<n; p+=stride){
        const float* q = pts + (size_t)p*6;
        float b=q[0], x=q[1], y=q[2], z=q[3];
        float fx = __fdiv_rn(x + 51.2f, 0.4f);
        float fy = __fdiv_rn(y + 51.2f, 0.4f);
        bool m = (fx >= 0.f) && (fx < 256.f) && (fy >= 0.f) && (fy < 256.f);
        int cix=(int)fx, ciy=(int)fy;
        int bi=(int)b;
        int key = m ? ((bi*GX + cix)*GY + ciy) : SENTKEY;
        g_keys[p]=key;
        atomicAdd(&g_cnt[key],1);
        atomicAdd(&g_sumxyz[key*3+0],x);
        atomicAdd(&g_sumxyz[key*3+1],y);
        atomicAdd(&g_sumxyz[key*3+2],z);
    }
}

// ---------------- B: two-level scan over keys ----------------
__global__ void kB1(){
    int tid = threadIdx.x;
    int idx = blockIdx.x*1024 + tid;
    int c = (idx<NKEY)? g_cnt[idx] : 0;
    int p = (c>0)? 1:0;
    #pragma unroll
    for (int o=16;o;o>>=1){ p+=__shfl_down_sync(FULLMASK,p,o); c+=__shfl_down_sync(FULLMASK,c,o); }
    __shared__ int sp[32], sc[32];
    if ((tid&31)==0){ sp[tid>>5]=p; sc[tid>>5]=c; }
    __syncthreads();
    if (tid<32){
        p=sp[tid]; c=sc[tid];
        #pragma unroll
        for (int o=16;o;o>>=1){ p+=__shfl_down_sync(FULLMASK,p,o); c+=__shfl_down_sync(FULLMASK,c,o); }
        if (tid==0){ g_blkP[blockIdx.x]=p; g_blkC[blockIdx.x]=c; }
    }
}

__global__ void kB2(){
    __shared__ int sp[512], sc[512];
    int t = threadIdx.x;
    int p = (t<NBLK)? g_blkP[t]:0;
    int c = (t<NBLK)? g_blkC[t]:0;
    sp[t]=p; sc[t]=c; __syncthreads();
    for (int o=1;o<512;o<<=1){
        int vp=(t>=o)?sp[t-o]:0, vc=(t>=o)?sc[t-o]:0;
        __syncthreads();
        sp[t]+=vp; sc[t]+=vc;
        __syncthreads();
    }
    if (t<NBLK){ g_offP[t]=sp[t]-p; g_offC[t]=sc[t]-c; }
    if (t==NBLK-1) g_U = sp[t];
}

__global__ void kB3(float* __restrict__ out){
    __shared__ int sp[1024], sc[1024];
    int tid = threadIdx.x;
    int idx = blockIdx.x*1024 + tid;
    int c = (idx<NKEY)? g_cnt[idx]:0;
    int pr = (c>0)? 1:0;
    sp[tid]=pr; sc[tid]=c; __syncthreads();
    for (int o=1;o<1024;o<<=1){
        int vp=(tid>=o)?sp[tid-o]:0, vc=(tid>=o)?sc[tid-o]:0;
        __syncthreads();
        sp[tid]+=vp; sc[tid]+=vc;
        __syncthreads();
    }
    if (idx<NKEY){
        int r  = sp[tid]-pr + g_offP[blockIdx.x];
        int of = sc[tid]-c  + g_offC[blockIdx.x];
        g_rank[idx]=r; g_off[idx]=of;
        if (pr){
            g_keyofrank[r]=idx; g_segstart[r]=of; g_segcnt[r]=c;
            float fc = (float)c;
            g_mean[r*3+0]=__fdiv_rn(g_sumxyz[idx*3+0],fc);
            g_mean[r*3+1]=__fdiv_rn(g_sumxyz[idx*3+1],fc);
            g_mean[r*3+2]=__fdiv_rn(g_sumxyz[idx*3+2],fc);
            int b=idx>>16, cx=(idx>>8)&255, cy=idx&255;
            float* oc = out + (size_t)NSEG*128 + (size_t)r*3;
            oc[0]=(float)b; oc[1]=(float)cy; oc[2]=(float)cx;
            if (idx==SENTKEY){ g_sentseg=r; g_nsent=c; }
        }
    }
}

__global__ void kZeroSent(){
    int ss = g_sentseg;
    if (ss >= 0) g_xm0u[(size_t)ss*32 + threadIdx.x] = ENC_NEG_INF;
}

// ---------------- CX: fused counting-sort scatter + x0pre + BN0 partials ----------------
__global__ void __launch_bounds__(256) kCX(const float* __restrict__ pts,
                                           const float* __restrict__ w0, int n){
    __shared__ float w0s[320];
    __shared__ float bs[64];
    int tid = threadIdx.x;
    if (tid < 64) bs[tid] = 0.f;
    for (int i=tid;i<320;i+=256) w0s[i] = w0[i];
    __syncthreads();

    float s[32], s2[32];
    #pragma unroll
    for (int c=0;c<32;c++){ s[c]=0.f; s2[c]=0.f; }

    int i0 = blockIdx.x*blockDim.x + tid;
    int stride = gridDim.x*blockDim.x;
    for (int p=i0; p<n; p+=stride){
        const float2* q = reinterpret_cast<const float2*>(pts + (size_t)p*6);
        float2 q0=__ldg(q), q1=__ldg(q+1), q2=__ldg(q+2);
        float x=q0.y, y=q1.x, z=q1.y;
        int key = g_keys[p];
        int pos = g_off[key] + atomicAdd(&g_cursor[key],1);
        int r = g_rank[key];
        g_segof[pos] = r;
        float mx=g_mean[r*3+0], my=g_mean[r*3+1], mzv=g_mean[r*3+2];
        float fx=__fdiv_rn(x + 51.2f, 0.4f);
        float fy=__fdiv_rn(y + 51.2f, 0.4f);
        int cix=(int)fx, ciy=(int)fy;
        float ccx=(float)cix*0.4f + 0.2f - 51.2f;
        float ccy=(float)ciy*0.4f + 0.2f - 51.2f;
        float f[10];
        f[0]=x; f[1]=y; f[2]=z; f[3]=q2.x; f[4]=q2.y;
        f[5]=x-mx; f[6]=y-my; f[7]=z-mzv;
        f[8]=x-ccx; f[9]=y-ccy;
        bool valid = (key != SENTKEY);
        float* dst = g_x0all + (size_t)pos*32;
        #pragma unroll
        for (int cq=0;cq<8;cq++){
            float4 v;
            float vv[4];
            #pragma unroll
            for (int t=0;t<4;t++){
                int c = cq*4+t;
                float a = 0.f;
                #pragma unroll
                for (int j=0;j<10;j++) a = fmaf(f[j], w0s[j*32+c], a);
                vv[t] = a;
                if (valid){ s[c] += a; s2[c] = fmaf(a,a,s2[c]); }
            }
            v.x=vv[0]; v.y=vv[1]; v.z=vv[2]; v.w=vv[3];
            reinterpret_cast<float4*>(dst)[cq] = v;
        }
    }
    int lane = tid&31;
    #pragma unroll
    for (int c=0;c<32;c++){
        float v=s[c], w=s2[c];
        #pragma unroll
        for (int o=16;o;o>>=1){ v+=__shfl_down_sync(FULLMASK,v,o); w+=__shfl_down_sync(FULLMASK,w,o); }
        if (lane==0){ atomicAdd(&bs[c], v); atomicAdd(&bs[32+c], w); }
    }
    __syncthreads();
    if (tid < 64) g_bn0part[blockIdx.x*64+tid] = bs[tid];
}

// ---------------- D1: BN0 params from partials ----------------
__global__ void kD1(const float* __restrict__ g0, const float* __restrict__ b0, int n){
    __shared__ double smd[512];
    int tid = threadIdx.x;   // 512
    int j = tid & 63, h = tid >> 6;   // 8 chunks
    double acc = 0.0;
    for (int b=h; b<NB_CX; b+=8) acc += (double)g_bn0part[b*64+j];
    smd[tid] = acc;
    __syncthreads();
    if (tid < 64){
        double v = 0.0;
        #pragma unroll
        for (int hh=0; hh<8; hh++) v += smd[hh*64 + tid];
        smd[tid] = v;
    }
    __syncthreads();
    if (tid < 32){
        double cnt = (double)(n - g_cnt[SENTKEY]);
        double mu = smd[tid]/cnt;
        double var = smd[32+tid]/cnt - mu*mu;
        if (var < 0.0) var = 0.0;
        float a = g0[tid] / sqrtf((float)var + BN_EPS);
        g_a0[tid]=a; g_b0v[tid]=b0[tid]-(float)mu*a;
    }
}

// ---------------- M1v2: streaming per-seg max of pre-affine x0 ----------------
__global__ void __launch_bounds__(256) kM1v2(){
    int gtid = blockIdx.x*blockDim.x + threadIdx.x;
    int w = gtid>>5, lane = gtid&31;
    int nwarps = (gridDim.x*blockDim.x)>>5;
    int U=g_U, ss=g_sentseg;
    for (int r=w; r<U; r+=nwarps){
        if (r==ss) continue;
        int st=g_segstart[r], cn=g_segcnt[r];
        const float* ptr = g_x0all + (size_t)st*32 + lane;
        float m=-INFINITY;
        int i=0;
        for (; i+4<=cn; i+=4){
            float a=ptr[(i+0)*32], b=ptr[(i+1)*32], c=ptr[(i+2)*32], d=ptr[(i+3)*32];
            m = fmaxf(m, fmaxf(fmaxf(a,b),fmaxf(c,d)));
        }
        for (; i<cn; i++) m = fmaxf(m, ptr[i*32]);
        g_xm0u[(size_t)r*32+lane] = encf(m);
    }
    int nsent = g_nsent;
    if (nsent>0 && blockIdx.x < 64){
        int st = g_segstart[ss];
        int w2 = blockIdx.x*8 + (threadIdx.x>>5);  // 0..511
        float m=-INFINITY;
        for (int i=w2;i<nsent;i+=512)
            m = fmaxf(m, g_x0all[(size_t)(st+i)*32+lane]);
        atomicMax(&g_xm0u[(size_t)ss*32+lane], encf(m));
    }
}

// ---------------- ZB: per-segment zb = relu(affine(xm0pre)) @ w1b ----------------
__global__ void __launch_bounds__(256) kZB(const float* __restrict__ w1){
    __shared__ float xs[32*136];
    __shared__ float ws[32*128];
    __shared__ float a0s[32], b0s[32];
    int U = g_U;
    int base = blockIdx.x*128;
    if (base >= U) return;
    int ns = min(128, U - base);
    int tid = threadIdx.x;
    if (tid < 32){ a0s[tid]=g_a0[tid]; b0s[tid]=g_b0v[tid]; }
    __syncthreads();
    for (int i=tid; i<1024; i+=256)
        reinterpret_cast<float4*>(ws)[i] = reinterpret_cast<const float4*>(w1)[1024+i]; // w1 rows 32..63
    for (int i=tid; i<1024; i+=256){
        int s = i>>3, q = i&7;
        uint4 u = (s<ns) ? reinterpret_cast<const uint4*>(g_xm0u + (size_t)(base+s)*32)[q]
                         : make_uint4(ENC_NEG_INF,ENC_NEG_INF,ENC_NEG_INF,ENC_NEG_INF);
        int c0 = q*4;
        xs[(c0+0)*136+s]=fmaxf(fmaf(a0s[c0+0],decf(u.x),b0s[c0+0]),0.f);
        xs[(c0+1)*136+s]=fmaxf(fmaf(a0s[c0+1],decf(u.y),b0s[c0+1]),0.f);
        xs[(c0+2)*136+s]=fmaxf(fmaf(a0s[c0+2],decf(u.z),b0s[c0+2]),0.f);
        xs[(c0+3)*136+s]=fmaxf(fmaf(a0s[c0+3],decf(u.w),b0s[c0+3]),0.f);
    }
    __syncthreads();
    int tc = tid & 15, tp = tid >> 4;
    float acc[8][8];
    #pragma unroll
    for (int i=0;i<8;i++)
        #pragma unroll
        for (int j=0;j<8;j++) acc[i][j]=0.f;
    #pragma unroll 8
    for (int k=0;k<32;k++){
        float4 a0v = *reinterpret_cast<float4*>(&xs[k*136 + tp*8]);
        float4 a1v = *reinterpret_cast<float4*>(&xs[k*136 + tp*8 + 4]);
        float4 b0v4 = *reinterpret_cast<float4*>(&ws[k*128 + tc*8]);
        float4 b1v4 = *reinterpret_cast<float4*>(&ws[k*128 + tc*8 + 4]);
        float a[8]={a0v.x,a0v.y,a0v.z,a0v.w,a1v.x,a1v.y,a1v.z,a1v.w};
        float b[8]={b0v4.x,b0v4.y,b0v4.z,b0v4.w,b1v4.x,b1v4.y,b1v4.z,b1v4.w};
        #pragma unroll
        for (int i=0;i<8;i++)
            #pragma unroll
            for (int j=0;j<8;j++) acc[i][j] = fmaf(a[i], b[j], acc[i][j]);
    }
    #pragma unroll
    for (int i=0;i<8;i++){
        int s = tp*8 + i;
        if (s < ns){
            float* dst = g_zb + (size_t)(base+s)*128 + tc*8;
            *reinterpret_cast<float4*>(dst)   = make_float4(acc[i][0],acc[i][1],acc[i][2],acc[i][3]);
            *reinterpret_cast<float4*>(dst+4) = make_float4(acc[i][4],acc[i][5],acc[i][6],acc[i][7]);
        }
    }
}

// ---------------- M2: za GEMM + fused segmented max + BN1 partials ----------------
// smem floats: zs 16896 | w1s 4096 | a0b0 64 | srA 256 | srB 256 | segs 132 -> 21700 floats
#define M2_SMEM_BYTES (21700*4)
__global__ void __launch_bounds__(256) kM2(const float* __restrict__ w1, int n){
    extern __shared__ float dsm[];
    float* zs   = dsm;                 // 128*132
    float* x0s  = dsm;                 // alias; consumed before zs written
    float* w1s  = dsm + 16896;         // 4096
    float* a0s  = dsm + 20992;         // 32
    float* b0s  = dsm + 21024;         // 32
    float* srA  = dsm + 21056;         // 256
    float* srB  = dsm + 21312;         // 256
    int*   segs = (int*)(dsm + 21568); // 132

    int tid = threadIdx.x;
    int base = blockIdx.x * 128;
    if (base >= n) return;
    int npts = min(128, n - base);

    if (tid < 32){ a0s[tid]=g_a0[tid]; b0s[tid]=g_b0v[tid]; }
    __syncthreads();

    for (int i=tid; i<1024; i+=256)
        reinterpret_cast<float4*>(w1s)[i] = reinterpret_cast<const float4*>(w1)[i];
    for (int i=tid; i<1024; i+=256){
        int pt = i>>3, q = i&7;
        float4 v = (pt<npts) ? reinterpret_cast<const float4*>(g_x0all + (size_t)(base+pt)*32)[q]
                             : make_float4(0.f,0.f,0.f,0.f);
        int c0 = q*4;
        x0s[(c0+0)*136+pt]=fmaxf(fmaf(a0s[c0+0],v.x,b0s[c0+0]),0.f);
        x0s[(c0+1)*136+pt]=fmaxf(fmaf(a0s[c0+1],v.y,b0s[c0+1]),0.f);
        x0s[(c0+2)*136+pt]=fmaxf(fmaf(a0s[c0+2],v.z,b0s[c0+2]),0.f);
        x0s[(c0+3)*136+pt]=fmaxf(fmaf(a0s[c0+3],v.w,b0s[c0+3]),0.f);
    }
    for (int i=tid; i<130; i+=256){
        int g = base + i - 1;
        segs[i] = (g >= 0 && g < n) ? g_segof[g] : -1;
    }
    __syncthreads();

    int tc = tid & 15, tp = tid >> 4;
    float acc[8][8];
    #pragma unroll
    for (int i=0;i<8;i++)
        #pragma unroll
        for (int j=0;j<8;j++) acc[i][j]=0.f;
    #pragma unroll 8
    for (int k=0;k<32;k++){
        float4 a0v = *reinterpret_cast<float4*>(&x0s[k*136 + tp*8]);
        float4 a1v = *reinterpret_cast<float4*>(&x0s[k*136 + tp*8 + 4]);
        float4 b0v4 = *reinterpret_cast<float4*>(&w1s[k*128 + tc*8]);
        float4 b1v4 = *reinterpret_cast<float4*>(&w1s[k*128 + tc*8 + 4]);
        float a[8]={a0v.x,a0v.y,a0v.z,a0v.w,a1v.x,a1v.y,a1v.z,a1v.w};
        float b[8]={b0v4.x,b0v4.y,b0v4.z,b0v4.w,b1v4.x,b1v4.y,b1v4.z,b1v4.w};
        #pragma unroll
        for (int i=0;i<8;i++)
            #pragma unroll
            for (int j=0;j<8;j++) acc[i][j] = fmaf(a[i], b[j], acc[i][j]);
    }
    __syncthreads();   // all x0s reads done before aliased zs writes
    #pragma unroll
    for (int i=0;i<8;i++){
        float* dst = &zs[(tp*8+i)*132 + tc*8];
        *reinterpret_cast<float4*>(dst)   = make_float4(acc[i][0],acc[i][1],acc[i][2],acc[i][3]);
        *reinterpret_cast<float4*>(dst+4) = make_float4(acc[i][4],acc[i][5],acc[i][6],acc[i][7]);
    }
    __syncthreads();

    // segmented scan: thread = (channel c, half h), up to 64 points serial
    int c = tid & 127, h = tid >> 7;
    int l0 = h*64, l1 = min(l0+64, npts);
    float sz = 0.f, sz2 = 0.f;
    if (l0 < l1){
        int nvalid = n - g_nsent;
        int rcur = segs[l0+1];
        bool openL = (segs[l0] == rcur);
        float zb = g_zb[(size_t)rcur*128 + c];
        float mza = -INFINITY;
        for (int i=l0; i<l1; i++){
            float za = zs[i*132 + c];
            float z = za + zb;
            if (base + i < nvalid){ sz += z; sz2 = fmaf(z,z,sz2); }
            mza = fmaxf(mza, za);
            int rn = segs[i+2];
            bool last = (i == l1-1);
            if (rn != rcur || last){
                bool openR = last && (rn == rcur);
                unsigned e = encf(mza + zb);
                unsigned* dst = &g_pre_u[(size_t)rcur*128 + c];
                if (openL | openR) atomicMax(dst, e);
                else *dst = e;
                if (!last && rn != rcur){
                    rcur = rn;
                    zb = g_zb[(size_t)rcur*128 + c];
                    mza = -INFINITY;
                    openL = false;
                }
            }
        }
    }
    srA[tid] = sz; srB[tid] = sz2;
    __syncthreads();
    if (tid < 128){
        g_bn1part[(size_t)blockIdx.x*256 + tid]       = srA[tid] + srA[tid+128];
        g_bn1part[(size_t)blockIdx.x*256 + 128 + tid] = srB[tid] + srB[tid+128];
    }
}

// ---------------- E1: BN1 params from partials ----------------
__global__ void kE1(const float* __restrict__ g1, const float* __restrict__ b1, int n, int nb){
    __shared__ double smd[2048];
    int tid = threadIdx.x;   // 1024
    int c = tid & 127, h = tid >> 7;  // 8 chunks
    double sz=0.0, sz2=0.0;
    for (int b=h; b<nb; b+=8){
        sz  += (double)g_bn1part[(size_t)b*256 + c];
        sz2 += (double)g_bn1part[(size_t)b*256 + 128 + c];
    }
    smd[tid] = sz; smd[1024+tid] = sz2;
    __syncthreads();
    if (tid < 128){
        double a=0.0, v=0.0;
        #pragma unroll
        for (int hh=0; hh<8; hh++){ a += smd[hh*128+tid]; v += smd[1024+hh*128+tid]; }
        double cnt = (double)(n - g_cnt[SENTKEY]);
        double mu = a/cnt;
        double var = v/cnt - mu*mu;
        if (var < 0.0) var = 0.0;
        float sc = g1[tid] / sqrtf((float)var + BN_EPS);
        g_a1[tid]=sc; g_b1v[tid]=b1[tid]-(float)mu*sc;
    }
}

// ---------------- final output ----------------
__global__ void kFinal(float* __restrict__ out){
    int i = blockIdx.x*blockDim.x + threadIdx.x;
    int stride = gridDim.x*blockDim.x;
    int U = g_U;
    const size_t total = (size_t)NSEG*128;
    for (size_t idx=i; idx<total; idx+=stride){
        int r = (int)(idx>>7), c = (int)(idx&127);
        float v = 0.f;
        if (r < U){
            float z = decf(g_pre_u[idx]);
            v = fmaxf(g_a1[c]*z + g_b1v[c], 0.f);
        }
        out[idx] = v;
    }
}

extern "C" void kernel_launch(void* const* d_in, const int* in_sizes, int n_in,
                              void* d_out, int out_size) {
    const float* pts = (const float*)d_in[0];
    const float* w0  = (const float*)d_in[1];
    const float* g0  = (const float*)d_in[2];
    const float* b0  = (const float*)d_in[3];
    const float* w1  = (const float*)d_in[4];
    const float* g1  = (const float*)d_in[5];
    const float* b1  = (const float*)d_in[6];
    float* out = (float*)d_out;
    int n = in_sizes[0] / 6;
    if (n > MAXN) n = MAXN;
    if (n <= 0) return;
    int nb = (n + 127) / 128;

    (void)cudaFuncSetAttribute(kM2, cudaFuncAttributeMaxDynamicSharedMemorySize, M2_SMEM_BYTES);
    (void)cudaGetLastError();

    kInit<<<4096, 256>>>();
    kFill<<<1024, 256>>>(out);
    kA<<<2048, 256>>>(pts, n);
    kB1<<<NBLK, 1024>>>();
    kB2<<<1, 512>>>();
    kB3<<<NBLK, 1024>>>(out);
    kZeroSent<<<1, 32>>>();
    kCX<<<NB_CX, 256>>>(pts, w0, n);
    kD1<<<1, 512>>>(g0, b0, n);
    kM1v2<<<1184, 256>>>();
    kZB<<<(NSEG+127)/128, 256>>>(w1);
    kM2<<<nb, 256, M2_SMEM_BYTES>>>(w1, n);
    kE1<<<1, 1024>>>(g1, b1, n, nb);
    kFinal<<<8192, 256>>>(out);
}